// round 5
// baseline (speedup 1.0000x reference)
#include <cuda_runtime.h>
#include <math.h>

#define D 128
#define SEGS 32
#define ROWS_PER_BLOCK 128
#define GROWS 64            // rows per gate block

// Scratch — zero-initialized at module load; mlp_kernel re-zeroes at its end
// so every launch (correctness, capture, replay) starts clean.
__device__ __align__(16) float g_sums[SEGS * D];
__device__ float g_cnt[SEGS];
__device__ __align__(16) float g_gateV[SEGS * D];
__device__ __align__(16) float g_gateE[SEGS * D];

// ---------------------------------------------------------------------------
// Segment sums over sorted batch_id. 256 threads = 8 warps per 128 rows
// (2x the warps of R3 — occupancy was the binding constraint: 22.6%).
// Fast path (block fully inside one segment, ~97% of blocks): warp w
// accumulates float4 over rows r0+w, r0+w+8, ... (16 iters, unrolled 4 so
// loads front-batch), cross-warp smem reduce, 128 atomics per block.
__global__ void __launch_bounds__(256) seg_sum_kernel(
    const float* __restrict__ x, const int* __restrict__ bid, int N) {
    int r0 = blockIdx.x * ROWS_PER_BLOCK;
    if (r0 >= N) return;
    int r1 = min(r0 + ROWS_PER_BLOCK, N);
    int t = threadIdx.x;

    int s0 = __ldg(&bid[r0]);
    int s1 = __ldg(&bid[r1 - 1]);

    if (s0 == s1) {
        __shared__ float sred[8][D];
        int w = t >> 5, l = t & 31;
        const float4* xf4 = (const float4*)x;   // 32 float4 per row
        float4 acc = make_float4(0.f, 0.f, 0.f, 0.f);
#pragma unroll 4
        for (int r = r0 + w; r < r1; r += 8) {
            float4 v = xf4[(size_t)r * 32 + l];
            acc.x += v.x; acc.y += v.y; acc.z += v.z; acc.w += v.w;
        }
        *(float4*)&sred[w][l * 4] = acc;
        __syncthreads();
        if (t < D) {
            float s = sred[0][t] + sred[1][t] + sred[2][t] + sred[3][t]
                    + sred[4][t] + sred[5][t] + sred[6][t] + sred[7][t];
            atomicAdd(&g_sums[s0 * D + t], s);
            if (t == 0) atomicAdd(&g_cnt[s0], (float)(r1 - r0));
        }
    } else {
        // slow path: per-row scalar with boundary flushes (rare blocks);
        // lower 128 threads carry it, upper half idles (block-uniform branch).
        if (t < D) {
            float acc = 0.0f, cnt = 0.0f;
            int cur = s0;
            for (int r = r0; r < r1; r++) {
                int s = __ldg(&bid[r]);
                if (s != cur) {
                    atomicAdd(&g_sums[cur * D + t], acc);
                    if (t == 0) atomicAdd(&g_cnt[cur], cnt);
                    acc = 0.0f; cnt = 0.0f; cur = s;
                }
                acc += x[(size_t)r * D + t];
                cnt += 1.0f;
            }
            atomicAdd(&g_sums[cur * D + t], acc);
            if (t == 0) atomicAdd(&g_cnt[cur], cnt);
        }
    }
}

// ---------------------------------------------------------------------------
// MLPs: 32 blocks (one per segment) x 512 threads. Each output's 128-term dot
// is split 4 ways across thread-groups (32 loads + 32 FMAs each), smem reduce.
// gate_V = sig(mlpV(c_V)); c_V2 = c_V*gate_V (exact: gate const per segment,
// mean linear); gate_E = sig(mlpE(c_V2)). Re-zeroes scratch at the end.
__device__ __forceinline__ void mlp_layer(
    const float* __restrict__ sin, float* __restrict__ sout,
    const float* __restrict__ W, const float* __restrict__ b,
    float (*sred)[D], int t128, int part, bool do_relu) {
    float p = 0.0f;
    const float* Wp = W + (part * 32) * D + t128;
    const float* xp = sin + part * 32;
#pragma unroll
    for (int k = 0; k < 32; k++)
        p = fmaf(xp[k], __ldg(&Wp[k * D]), p);
    sred[part][t128] = p;
    __syncthreads();
    if (part == 0) {
        float v = sred[0][t128] + sred[1][t128] + sred[2][t128] + sred[3][t128]
                + __ldg(&b[t128]);
        sout[t128] = do_relu ? fmaxf(v, 0.0f) : v;
    }
    __syncthreads();
}

__global__ void __launch_bounds__(512) mlp_kernel(
    const float* __restrict__ VW1, const float* __restrict__ Vb1,
    const float* __restrict__ VW2, const float* __restrict__ Vb2,
    const float* __restrict__ VW3, const float* __restrict__ Vb3,
    const float* __restrict__ EW1, const float* __restrict__ Eb1,
    const float* __restrict__ EW2, const float* __restrict__ Eb2,
    const float* __restrict__ EW3, const float* __restrict__ Eb3) {
    __shared__ float scv[D], bufA[D], bufB[D];
    __shared__ float sred[4][D];
    int seg = blockIdx.x;
    int t = threadIdx.x;
    int t128 = t & 127;
    int part = t >> 7;

    if (t < D) {
        float cnt = fmaxf(g_cnt[seg], 1.0f);
        float cv = g_sums[seg * D + t] / cnt;
        scv[t] = cv;
    }
    __syncthreads();

    // --- V MLP ---
    mlp_layer(scv,  bufA, VW1, Vb1, sred, t128, part, true);
    mlp_layer(bufA, bufB, VW2, Vb2, sred, t128, part, true);
    mlp_layer(bufB, bufA, VW3, Vb3, sred, t128, part, false);
    if (t < D) {
        float gV = 1.0f / (1.0f + expf(-bufA[t]));
        g_gateV[seg * D + t] = gV;
        bufB[t] = scv[t] * gV;     // c_V2
    }
    __syncthreads();

    // --- E MLP ---
    mlp_layer(bufB, bufA, EW1, Eb1, sred, t128, part, true);
    mlp_layer(bufA, bufB, EW2, Eb2, sred, t128, part, true);
    mlp_layer(bufB, bufA, EW3, Eb3, sred, t128, part, false);
    if (t < D) {
        g_gateE[seg * D + t] = 1.0f / (1.0f + expf(-bufA[t]));
        // restore scratch for the next launch (zero-invariant at entry)
        g_sums[seg * D + t] = 0.0f;
        if (t == 0) g_cnt[seg] = 0.0f;
    }
}

// ---------------------------------------------------------------------------
// Combined gating. Blocks [0, nodeBlocks) gate nodes (dst_na L2-hot from
// seg_sum — plain loads), the rest gate edges (pure streaming — __ldcs/__stcs
// to avoid thrashing L2). 64 rows/block; segment ids staged in smem.
__global__ void __launch_bounds__(256) gate_kernel(
    const float* __restrict__ x, const float* __restrict__ ea,
    const int* __restrict__ eidx, const int* __restrict__ bid,
    float* __restrict__ outN, float* __restrict__ outE,
    int N, int E, int nodeBlocks) {
    __shared__ int ssid[GROWS];
    int t = threadIdx.x;
    int b = blockIdx.x;

    if (b < nodeBlocks) {
        int r0 = b * GROWS;
        if (t < GROWS) {
            int r = r0 + t;
            ssid[t] = (r < N) ? __ldg(&bid[r]) : 0;
        }
        __syncthreads();
        const float4* src = (const float4*)x;
        float4* dst = (float4*)outN;
        long long base = (long long)r0 * 32;
#pragma unroll
        for (int it = 0; it < 8; it++) {
            int i = it * 256 + t;
            int r = r0 + (i >> 5);
            if (r < N) {
                int s = ssid[i >> 5];
                float4 g = *(const float4*)&g_gateV[s * D + (i & 31) * 4];
                float4 v = src[base + i];
                v.x *= g.x; v.y *= g.y; v.z *= g.z; v.w *= g.w;
                __stcs(&dst[base + i], v);
            }
        }
    } else {
        int r0 = (b - nodeBlocks) * GROWS;
        if (t < GROWS) {
            int r = r0 + t;
            ssid[t] = (r < E) ? __ldg(&bid[__ldg(&eidx[r])]) : 0;
        }
        __syncthreads();
        const float4* src = (const float4*)ea;
        float4* dst = (float4*)outE;
        long long base = (long long)r0 * 32;
#pragma unroll
        for (int it = 0; it < 8; it++) {
            int i = it * 256 + t;
            int r = r0 + (i >> 5);
            if (r < E) {
                int s = ssid[i >> 5];
                float4 g = *(const float4*)&g_gateE[s * D + (i & 31) * 4];
                float4 v = __ldcs(&src[base + i]);
                v.x *= g.x; v.y *= g.y; v.z *= g.z; v.w *= g.w;
                __stcs(&dst[base + i], v);
            }
        }
    }
}

// ---------------------------------------------------------------------------
extern "C" void kernel_launch(void* const* d_in, const int* in_sizes, int n_in,
                              void* d_out, int out_size) {
    const float* dst_na  = (const float*)d_in[0];
    const float* ea      = (const float*)d_in[1];
    const int*   eidx    = (const int*)d_in[2];   // [2, E], row 0 = src
    const int*   bid     = (const int*)d_in[3];
    const float* VW1 = (const float*)d_in[4];
    const float* Vb1 = (const float*)d_in[5];
    const float* VW2 = (const float*)d_in[6];
    const float* Vb2 = (const float*)d_in[7];
    const float* VW3 = (const float*)d_in[8];
    const float* Vb3 = (const float*)d_in[9];
    const float* EW1 = (const float*)d_in[10];
    const float* Eb1 = (const float*)d_in[11];
    const float* EW2 = (const float*)d_in[12];
    const float* Eb2 = (const float*)d_in[13];
    const float* EW3 = (const float*)d_in[14];
    const float* Eb3 = (const float*)d_in[15];

    int N = in_sizes[0] / D;
    int E = in_sizes[1] / D;
    float* out_nodes = (float*)d_out;
    float* out_edges = (float*)d_out + (size_t)N * D;

    int sum_blocks = (N + ROWS_PER_BLOCK - 1) / ROWS_PER_BLOCK;
    seg_sum_kernel<<<sum_blocks, 256>>>(dst_na, bid, N);

    mlp_kernel<<<SEGS, 512>>>(VW1, Vb1, VW2, Vb2, VW3, Vb3,
                              EW1, Eb1, EW2, Eb2, EW3, Eb3);

    int nodeBlocks = (N + GROWS - 1) / GROWS;
    int edgeBlocks = (E + GROWS - 1) / GROWS;
    gate_kernel<<<nodeBlocks + edgeBlocks, 256>>>(
        dst_na, ea, eidx, bid, out_nodes, out_edges, N, E, nodeBlocks);
}

// round 6
// speedup vs baseline: 1.0326x; 1.0326x over previous
#include <cuda_runtime.h>
#include <math.h>

#define D 128
#define SEGS 32
#define SROWS 32            // rows per seg_sum block
#define GROWS 64            // rows per gate block

// Scratch — zero-initialized at module load; mlp_kernel re-zeroes at its end
// so every launch (correctness, capture, replay) starts clean.
__device__ __align__(16) float g_sums[SEGS * D];
__device__ float g_cnt[SEGS];
__device__ __align__(16) float g_gateV[SEGS * D];
__device__ __align__(16) float g_gateE[SEGS * D];

// ---------------------------------------------------------------------------
// Segment sums over sorted batch_id. 256 threads per 32 rows -> 3125 blocks
// (dense waves). Each thread: 4 fully-unrolled INDEPENDENT float4 loads
// (separate accumulators -> ptxas front-batches, MLP_p1=4), smem reduce,
// 128 atomics/block.
__global__ void __launch_bounds__(256) seg_sum_kernel(
    const float* __restrict__ x, const int* __restrict__ bid, int N) {
    int r0 = blockIdx.x * SROWS;
    if (r0 >= N) return;
    int rlast = min(r0 + SROWS, N) - 1;
    int t = threadIdx.x;

    int s0 = __ldg(&bid[r0]);
    int s1 = __ldg(&bid[rlast]);

    if (s0 == s1) {
        __shared__ float sred[8][D];
        int f4c = t & 31;            // float4 column 0..31
        int rg  = t >> 5;            // row group 0..7
        const float4* xf4 = (const float4*)x;   // 32 float4 per row
        size_t base = (size_t)(r0 + rg) * 32 + f4c;

        float4 a0, a1, a2, a3;
        if (r0 + SROWS <= N) {       // full block: unguarded, batched
            a0 = xf4[base];
            a1 = xf4[base + 8 * 32];
            a2 = xf4[base + 16 * 32];
            a3 = xf4[base + 24 * 32];
        } else {
            float4 z = make_float4(0.f, 0.f, 0.f, 0.f);
            a0 = (r0 + rg      < N) ? xf4[base]           : z;
            a1 = (r0 + rg + 8  < N) ? xf4[base + 8 * 32]  : z;
            a2 = (r0 + rg + 16 < N) ? xf4[base + 16 * 32] : z;
            a3 = (r0 + rg + 24 < N) ? xf4[base + 24 * 32] : z;
        }
        float4 acc;
        acc.x = (a0.x + a1.x) + (a2.x + a3.x);
        acc.y = (a0.y + a1.y) + (a2.y + a3.y);
        acc.z = (a0.z + a1.z) + (a2.z + a3.z);
        acc.w = (a0.w + a1.w) + (a2.w + a3.w);
        *(float4*)&sred[rg][f4c * 4] = acc;
        __syncthreads();
        if (t < D) {
            float s = (sred[0][t] + sred[1][t]) + (sred[2][t] + sred[3][t])
                    + (sred[4][t] + sred[5][t]) + (sred[6][t] + sred[7][t]);
            atomicAdd(&g_sums[s0 * D + t], s);
            if (t == 0) atomicAdd(&g_cnt[s0], (float)(rlast - r0 + 1));
        }
    } else {
        // slow path: segment boundary inside block (~1% of blocks);
        // lower 128 threads scalar-walk with boundary flushes.
        if (t < D) {
            float acc = 0.0f, cnt = 0.0f;
            int cur = s0;
            for (int r = r0; r <= rlast; r++) {
                int s = __ldg(&bid[r]);
                if (s != cur) {
                    atomicAdd(&g_sums[cur * D + t], acc);
                    if (t == 0) atomicAdd(&g_cnt[cur], cnt);
                    acc = 0.0f; cnt = 0.0f; cur = s;
                }
                acc += x[(size_t)r * D + t];
                cnt += 1.0f;
            }
            atomicAdd(&g_sums[cur * D + t], acc);
            if (t == 0) atomicAdd(&g_cnt[cur], cnt);
        }
    }
}

// ---------------------------------------------------------------------------
// MLPs: 32 blocks (one per segment) x 512 threads. Each output's 128-term dot
// is split 4 ways across thread-groups (32 loads + 32 FMAs each), smem reduce.
// gate_V = sig(mlpV(c_V)); c_V2 = c_V*gate_V (exact: gate const per segment,
// mean linear); gate_E = sig(mlpE(c_V2)). Re-zeroes scratch at the end.
__device__ __forceinline__ void mlp_layer(
    const float* __restrict__ sin, float* __restrict__ sout,
    const float* __restrict__ W, const float* __restrict__ b,
    float (*sred)[D], int t128, int part, bool do_relu) {
    float p = 0.0f;
    const float* Wp = W + (part * 32) * D + t128;
    const float* xp = sin + part * 32;
#pragma unroll
    for (int k = 0; k < 32; k++)
        p = fmaf(xp[k], __ldg(&Wp[k * D]), p);
    sred[part][t128] = p;
    __syncthreads();
    if (part == 0) {
        float v = sred[0][t128] + sred[1][t128] + sred[2][t128] + sred[3][t128]
                + __ldg(&b[t128]);
        sout[t128] = do_relu ? fmaxf(v, 0.0f) : v;
    }
    __syncthreads();
}

__global__ void __launch_bounds__(512) mlp_kernel(
    const float* __restrict__ VW1, const float* __restrict__ Vb1,
    const float* __restrict__ VW2, const float* __restrict__ Vb2,
    const float* __restrict__ VW3, const float* __restrict__ Vb3,
    const float* __restrict__ EW1, const float* __restrict__ Eb1,
    const float* __restrict__ EW2, const float* __restrict__ Eb2,
    const float* __restrict__ EW3, const float* __restrict__ Eb3) {
    __shared__ float scv[D], bufA[D], bufB[D];
    __shared__ float sred[4][D];
    int seg = blockIdx.x;
    int t = threadIdx.x;
    int t128 = t & 127;
    int part = t >> 7;

    if (t < D) {
        float cnt = fmaxf(g_cnt[seg], 1.0f);
        float cv = g_sums[seg * D + t] / cnt;
        scv[t] = cv;
    }
    __syncthreads();

    // --- V MLP ---
    mlp_layer(scv,  bufA, VW1, Vb1, sred, t128, part, true);
    mlp_layer(bufA, bufB, VW2, Vb2, sred, t128, part, true);
    mlp_layer(bufB, bufA, VW3, Vb3, sred, t128, part, false);
    if (t < D) {
        float gV = 1.0f / (1.0f + expf(-bufA[t]));
        g_gateV[seg * D + t] = gV;
        bufB[t] = scv[t] * gV;     // c_V2
    }
    __syncthreads();

    // --- E MLP ---
    mlp_layer(bufB, bufA, EW1, Eb1, sred, t128, part, true);
    mlp_layer(bufA, bufB, EW2, Eb2, sred, t128, part, true);
    mlp_layer(bufB, bufA, EW3, Eb3, sred, t128, part, false);
    if (t < D) {
        g_gateE[seg * D + t] = 1.0f / (1.0f + expf(-bufA[t]));
        // restore scratch for the next launch (zero-invariant at entry)
        g_sums[seg * D + t] = 0.0f;
        if (t == 0) g_cnt[seg] = 0.0f;
    }
}

// ---------------------------------------------------------------------------
// Combined gating. Blocks [0, nodeBlocks) gate nodes (dst_na L2-hot from
// seg_sum — plain loads), the rest gate edges (pure streaming — __ldcs/__stcs
// to avoid thrashing L2). 64 rows/block; segment ids staged in smem.
__global__ void __launch_bounds__(256) gate_kernel(
    const float* __restrict__ x, const float* __restrict__ ea,
    const int* __restrict__ eidx, const int* __restrict__ bid,
    float* __restrict__ outN, float* __restrict__ outE,
    int N, int E, int nodeBlocks) {
    __shared__ int ssid[GROWS];
    int t = threadIdx.x;
    int b = blockIdx.x;

    if (b < nodeBlocks) {
        int r0 = b * GROWS;
        if (t < GROWS) {
            int r = r0 + t;
            ssid[t] = (r < N) ? __ldg(&bid[r]) : 0;
        }
        __syncthreads();
        const float4* src = (const float4*)x;
        float4* dst = (float4*)outN;
        long long base = (long long)r0 * 32;
#pragma unroll
        for (int it = 0; it < 8; it++) {
            int i = it * 256 + t;
            int r = r0 + (i >> 5);
            if (r < N) {
                int s = ssid[i >> 5];
                float4 g = *(const float4*)&g_gateV[s * D + (i & 31) * 4];
                float4 v = src[base + i];
                v.x *= g.x; v.y *= g.y; v.z *= g.z; v.w *= g.w;
                __stcs(&dst[base + i], v);
            }
        }
    } else {
        int r0 = (b - nodeBlocks) * GROWS;
        if (t < GROWS) {
            int r = r0 + t;
            ssid[t] = (r < E) ? __ldg(&bid[__ldg(&eidx[r])]) : 0;
        }
        __syncthreads();
        const float4* src = (const float4*)ea;
        float4* dst = (float4*)outE;
        long long base = (long long)r0 * 32;
#pragma unroll
        for (int it = 0; it < 8; it++) {
            int i = it * 256 + t;
            int r = r0 + (i >> 5);
            if (r < E) {
                int s = ssid[i >> 5];
                float4 g = *(const float4*)&g_gateE[s * D + (i & 31) * 4];
                float4 v = __ldcs(&src[base + i]);
                v.x *= g.x; v.y *= g.y; v.z *= g.z; v.w *= g.w;
                __stcs(&dst[base + i], v);
            }
        }
    }
}

// ---------------------------------------------------------------------------
extern "C" void kernel_launch(void* const* d_in, const int* in_sizes, int n_in,
                              void* d_out, int out_size) {
    const float* dst_na  = (const float*)d_in[0];
    const float* ea      = (const float*)d_in[1];
    const int*   eidx    = (const int*)d_in[2];   // [2, E], row 0 = src
    const int*   bid     = (const int*)d_in[3];
    const float* VW1 = (const float*)d_in[4];
    const float* Vb1 = (const float*)d_in[5];
    const float* VW2 = (const float*)d_in[6];
    const float* Vb2 = (const float*)d_in[7];
    const float* VW3 = (const float*)d_in[8];
    const float* Vb3 = (const float*)d_in[9];
    const float* EW1 = (const float*)d_in[10];
    const float* Eb1 = (const float*)d_in[11];
    const float* EW2 = (const float*)d_in[12];
    const float* Eb2 = (const float*)d_in[13];
    const float* EW3 = (const float*)d_in[14];
    const float* Eb3 = (const float*)d_in[15];

    int N = in_sizes[0] / D;
    int E = in_sizes[1] / D;
    float* out_nodes = (float*)d_out;
    float* out_edges = (float*)d_out + (size_t)N * D;

    int sum_blocks = (N + SROWS - 1) / SROWS;
    seg_sum_kernel<<<sum_blocks, 256>>>(dst_na, bid, N);

    mlp_kernel<<<SEGS, 512>>>(VW1, Vb1, VW2, Vb2, VW3, Vb3,
                              EW1, Eb1, EW2, Eb2, EW3, Eb3);

    int nodeBlocks = (N + GROWS - 1) / GROWS;
    int edgeBlocks = (E + GROWS - 1) / GROWS;
    gate_kernel<<<nodeBlocks + edgeBlocks, 256>>>(
        dst_na, ea, eidx, bid, out_nodes, out_edges, N, E, nodeBlocks);
}

// round 7
// speedup vs baseline: 1.0431x; 1.0101x over previous
#include <cuda_runtime.h>
#include <math.h>

#define D 128
#define SEGS 32
#define SROWS 64            // rows per seg_sum block
#define GROWS 64            // rows per gate block
#define CAP_E (1 << 20)     // static capacity for precomputed edge seg ids

// Scratch — zero-initialized at module load; fused kernel self-restores all
// mutable state at the end of every launch (capture/replay safe).
__device__ __align__(16) float g_sums[SEGS * D];
__device__ float g_cnt[SEGS];
__device__ __align__(16) float g_gateV[SEGS * D];
__device__ __align__(16) float g_gateE[SEGS * D];
__device__ int g_esid[CAP_E];
__device__ unsigned int g_done  = 0;
__device__ unsigned int g_done2 = 0;

// ---------------------------------------------------------------------------
// Fused pre-pass. One launch, three block roles:
//   [0, sumBlocks)                    : segment sums (64 rows, 8 f4 loads/thr)
//   [sumBlocks, sumBlocks+esidBlocks) : g_esid[e] = bid[eidx[e]]  (independent)
//   last SEGS blocks                  : prefetch MLP weights, spin on counter,
//                                       compute both gate MLPs, reset scratch.
__device__ __forceinline__ void mlp_layer256(
    const float* __restrict__ sin, float* __restrict__ sout,
    const float* __restrict__ W, const float* __restrict__ b,
    float (*sred)[D], int t128, int part, bool do_relu) {
    float p = 0.0f;
    const float* Wp = W + (part * 64) * D + t128;
    const float* xp = sin + part * 64;
#pragma unroll
    for (int k = 0; k < 64; k++)
        p = fmaf(xp[k], __ldg(&Wp[k * D]), p);
    sred[part][t128] = p;
    __syncthreads();
    if (part == 0) {
        float v = sred[0][t128] + sred[1][t128] + __ldg(&b[t128]);
        sout[t128] = do_relu ? fmaxf(v, 0.0f) : v;
    }
    __syncthreads();
}

__device__ __forceinline__ void prefetch_l2(const float* p, int bytes, int t) {
    for (int off = t * 128; off < bytes; off += 256 * 128)
        asm volatile("prefetch.global.L2 [%0];" ::
                     "l"((const char*)p + off));
}

__global__ void __launch_bounds__(256) fused_pre_kernel(
    const float* __restrict__ x, const int* __restrict__ bid,
    const int* __restrict__ eidx, int N, int E,
    int sumBlocks, int esidBlocks,
    const float* __restrict__ VW1, const float* __restrict__ Vb1,
    const float* __restrict__ VW2, const float* __restrict__ Vb2,
    const float* __restrict__ VW3, const float* __restrict__ Vb3,
    const float* __restrict__ EW1, const float* __restrict__ Eb1,
    const float* __restrict__ EW2, const float* __restrict__ Eb2,
    const float* __restrict__ EW3, const float* __restrict__ Eb3) {
    int b = blockIdx.x;
    int t = threadIdx.x;

    if (b < sumBlocks) {
        // ---------------- segment sums ----------------
        int r0 = b * SROWS;
        int rlast = min(r0 + SROWS, N) - 1;
        int s0 = __ldg(&bid[r0]);
        int s1 = __ldg(&bid[rlast]);

        if (s0 == s1) {
            __shared__ float sred[8][D];
            int f4c = t & 31;        // float4 column
            int rg  = t >> 5;        // row group 0..7
            const float4* xf4 = (const float4*)x;
            size_t base = (size_t)(r0 + rg) * 32 + f4c;
            float4 acc = make_float4(0.f, 0.f, 0.f, 0.f);
            if (r0 + SROWS <= N) {
                float4 a[8];
#pragma unroll
                for (int j = 0; j < 8; j++)
                    a[j] = xf4[base + (size_t)j * 8 * 32];
#pragma unroll
                for (int j = 0; j < 8; j++) {
                    acc.x += a[j].x; acc.y += a[j].y;
                    acc.z += a[j].z; acc.w += a[j].w;
                }
            } else {
#pragma unroll
                for (int j = 0; j < 8; j++) {
                    if (r0 + rg + j * 8 < N) {
                        float4 v = xf4[base + (size_t)j * 8 * 32];
                        acc.x += v.x; acc.y += v.y; acc.z += v.z; acc.w += v.w;
                    }
                }
            }
            *(float4*)&sred[rg][f4c * 4] = acc;
            __syncthreads();
            if (t < D) {
                float s = (sred[0][t] + sred[1][t]) + (sred[2][t] + sred[3][t])
                        + (sred[4][t] + sred[5][t]) + (sred[6][t] + sred[7][t]);
                atomicAdd(&g_sums[s0 * D + t], s);
                if (t == 0) atomicAdd(&g_cnt[s0], (float)(rlast - r0 + 1));
            }
        } else {
            // segment boundary inside block (rare): scalar walk on 128 thr
            if (t < D) {
                float acc = 0.0f, cnt = 0.0f;
                int cur = s0;
                for (int r = r0; r <= rlast; r++) {
                    int s = __ldg(&bid[r]);
                    if (s != cur) {
                        atomicAdd(&g_sums[cur * D + t], acc);
                        if (t == 0) atomicAdd(&g_cnt[cur], cnt);
                        acc = 0.0f; cnt = 0.0f; cur = s;
                    }
                    acc += x[(size_t)r * D + t];
                    cnt += 1.0f;
                }
                atomicAdd(&g_sums[cur * D + t], acc);
                if (t == 0) atomicAdd(&g_cnt[cur], cnt);
            }
        }
        // release: all block's atomics precede the counter bump
        __syncthreads();
        if (t == 0) {
            __threadfence();
            atomicAdd(&g_done, 1u);
        }
    } else if (b < sumBlocks + esidBlocks) {
        // ---------------- edge segment-id precompute ----------------
        int e0 = (b - sumBlocks) * 1024 + t * 4;
        if (e0 + 3 < E) {
            int4 ev = __ldg((const int4*)&eidx[e0]);
            int4 sv;
            sv.x = __ldg(&bid[ev.x]);
            sv.y = __ldg(&bid[ev.y]);
            sv.z = __ldg(&bid[ev.z]);
            sv.w = __ldg(&bid[ev.w]);
            *(int4*)&g_esid[e0] = sv;
        } else {
            for (int e = e0; e < E; e++)
                g_esid[e] = __ldg(&bid[__ldg(&eidx[e])]);
        }
    } else {
        // ---------------- MLP tail blocks (one per segment) ----------------
        int seg = b - sumBlocks - esidBlocks;
        // prefetch weights into L2 while seg-sum blocks run
        prefetch_l2(VW1, D * D * 4, t); prefetch_l2(VW2, D * D * 4, t);
        prefetch_l2(VW3, D * D * 4, t); prefetch_l2(EW1, D * D * 4, t);
        prefetch_l2(EW2, D * D * 4, t); prefetch_l2(EW3, D * D * 4, t);

        if (t == 0) {
            while (atomicAdd(&g_done, 0u) < (unsigned)sumBlocks)
                __nanosleep(64);
            __threadfence();   // acquire
        }
        __syncthreads();

        __shared__ float scv[D], bufA[D], bufB[D];
        __shared__ float sred[2][D];
        int t128 = t & 127;
        int part = t >> 7;

        if (t < D) {
            float cnt = fmaxf(g_cnt[seg], 1.0f);
            scv[t] = g_sums[seg * D + t] / cnt;
        }
        __syncthreads();

        // V MLP
        mlp_layer256(scv,  bufA, VW1, Vb1, sred, t128, part, true);
        mlp_layer256(bufA, bufB, VW2, Vb2, sred, t128, part, true);
        mlp_layer256(bufB, bufA, VW3, Vb3, sred, t128, part, false);
        if (t < D) {
            float gV = 1.0f / (1.0f + expf(-bufA[t]));
            g_gateV[seg * D + t] = gV;
            bufB[t] = scv[t] * gV;   // c_V2 = c_V * gate_V (exact identity)
        }
        __syncthreads();

        // E MLP
        mlp_layer256(bufB, bufA, EW1, Eb1, sred, t128, part, true);
        mlp_layer256(bufA, bufB, EW2, Eb2, sred, t128, part, true);
        mlp_layer256(bufB, bufA, EW3, Eb3, sred, t128, part, false);
        if (t < D) {
            g_gateE[seg * D + t] = 1.0f / (1.0f + expf(-bufA[t]));
            // restore scratch (zero-invariant at launch entry)
            g_sums[seg * D + t] = 0.0f;
            if (t == 0) g_cnt[seg] = 0.0f;
        }
        __syncthreads();
        if (t == 0) {
            __threadfence();
            unsigned old = atomicAdd(&g_done2, 1u);
            if (old == SEGS - 1) {   // last MLP block resets flags for replay
                g_done = 0u;
                g_done2 = 0u;
            }
        }
    }
}

// ---------------------------------------------------------------------------
// Gating. Blocks [0, nodeBlocks) gate nodes; rest gate edges. 64 rows/block,
// 8 float4 iterations; row index is warp-uniform so bid/esid loads are
// broadcasts — no smem, no barrier. Edges stream with __ldcs/__stcs.
__global__ void __launch_bounds__(256) gate_kernel(
    const float* __restrict__ x, const float* __restrict__ ea,
    const int* __restrict__ eidx, const int* __restrict__ bid,
    float* __restrict__ outN, float* __restrict__ outE,
    int N, int E, int nodeBlocks, int useEsid) {
    int t = threadIdx.x;
    int b = blockIdx.x;

    if (b < nodeBlocks) {
        int r0 = b * GROWS;
        const float4* src = (const float4*)x;
        float4* dst = (float4*)outN;
        long long base = (long long)r0 * 32;
#pragma unroll
        for (int it = 0; it < 8; it++) {
            int i = it * 256 + t;
            int r = r0 + (i >> 5);             // warp-uniform
            if (r < N) {
                int s = __ldg(&bid[r]);        // broadcast
                float4 g = *(const float4*)&g_gateV[s * D + (i & 31) * 4];
                float4 v = src[base + i];
                v.x *= g.x; v.y *= g.y; v.z *= g.z; v.w *= g.w;
                __stcs(&dst[base + i], v);
            }
        }
    } else {
        int r0 = (b - nodeBlocks) * GROWS;
        const float4* src = (const float4*)ea;
        float4* dst = (float4*)outE;
        long long base = (long long)r0 * 32;
#pragma unroll
        for (int it = 0; it < 8; it++) {
            int i = it * 256 + t;
            int r = r0 + (i >> 5);             // warp-uniform
            if (r < E) {
                int s = useEsid ? __ldg(&g_esid[r])
                                : __ldg(&bid[__ldg(&eidx[r])]);
                float4 g = *(const float4*)&g_gateE[s * D + (i & 31) * 4];
                float4 v = __ldcs(&src[base + i]);
                v.x *= g.x; v.y *= g.y; v.z *= g.z; v.w *= g.w;
                __stcs(&dst[base + i], v);
            }
        }
    }
}

// ---------------------------------------------------------------------------
extern "C" void kernel_launch(void* const* d_in, const int* in_sizes, int n_in,
                              void* d_out, int out_size) {
    const float* dst_na  = (const float*)d_in[0];
    const float* ea      = (const float*)d_in[1];
    const int*   eidx    = (const int*)d_in[2];   // [2, E], row 0 = src
    const int*   bid     = (const int*)d_in[3];
    const float* VW1 = (const float*)d_in[4];
    const float* Vb1 = (const float*)d_in[5];
    const float* VW2 = (const float*)d_in[6];
    const float* Vb2 = (const float*)d_in[7];
    const float* VW3 = (const float*)d_in[8];
    const float* Vb3 = (const float*)d_in[9];
    const float* EW1 = (const float*)d_in[10];
    const float* Eb1 = (const float*)d_in[11];
    const float* EW2 = (const float*)d_in[12];
    const float* Eb2 = (const float*)d_in[13];
    const float* EW3 = (const float*)d_in[14];
    const float* Eb3 = (const float*)d_in[15];

    int N = in_sizes[0] / D;
    int E = in_sizes[1] / D;
    float* out_nodes = (float*)d_out;
    float* out_edges = (float*)d_out + (size_t)N * D;

    int sumBlocks  = (N + SROWS - 1) / SROWS;
    int useEsid    = (E <= CAP_E) ? 1 : 0;
    int esidBlocks = useEsid ? (E + 1023) / 1024 : 0;

    fused_pre_kernel<<<sumBlocks + esidBlocks + SEGS, 256>>>(
        dst_na, bid, eidx, N, E, sumBlocks, esidBlocks,
        VW1, Vb1, VW2, Vb2, VW3, Vb3,
        EW1, Eb1, EW2, Eb2, EW3, Eb3);

    int nodeBlocks = (N + GROWS - 1) / GROWS;
    int edgeBlocks = (E + GROWS - 1) / GROWS;
    gate_kernel<<<nodeBlocks + edgeBlocks, 256>>>(
        dst_na, ea, eidx, bid, out_nodes, out_edges, N, E, nodeBlocks, useEsid);
}